// round 7
// baseline (speedup 1.0000x reference)
#include <cuda_runtime.h>
#include <cstdint>
#include <math.h>

#define BB    512
#define STATE 256
#define DES   128
#define H     512
#define SPLITS 18

#define STG   6      // per-warp B ring depth
#define BSW   36     // B stage row stride (words) -> conflict-free frag LDS
#define BSTW  (16 * BSW)          // words per B stage (576)
#define AW2   20     // A fp32 tile row stride (words)

// dynamic smem words: scales 8*128 + A 128*20 + B rings 8*STG*BSTW
#define SMEM_WORDS (1024 + 128 * AW2 + 8 * STG * BSTW)
#define SMEM_BYTES (SMEM_WORDS * 4)

__device__ float g_buf0[BB * H];
__device__ float g_buf1[BB * H];
__device__ float g_part[SPLITS][BB][H];

__device__ __forceinline__ uint32_t pack_h2(float lo, float hi) {
    uint32_t r;
    asm("cvt.rn.f16x2.f32 %0, %1, %2;" : "=r"(r) : "f"(hi), "f"(lo));
    return r;
}
__device__ __forceinline__ void mma16816(float* c,
                                         uint32_t a0, uint32_t a1, uint32_t a2, uint32_t a3,
                                         uint32_t b0, uint32_t b1) {
    asm volatile("mma.sync.aligned.m16n8k16.row.col.f32.f16.f16.f32 "
                 "{%0,%1,%2,%3}, {%4,%5,%6,%7}, {%8,%9}, {%0,%1,%2,%3};"
                 : "+f"(c[0]), "+f"(c[1]), "+f"(c[2]), "+f"(c[3])
                 : "r"(a0), "r"(a1), "r"(a2), "r"(a3), "r"(b0), "r"(b1));
}
__device__ __forceinline__ uint32_t smem_u32(const void* p) {
    uint32_t a;
    asm("{ .reg .u64 t; cvta.to.shared.u64 t, %1; cvt.u32.u64 %0, t; }" : "=r"(a) : "l"(p));
    return a;
}
__device__ __forceinline__ void cp16(uint32_t dst, const float* src) {
    asm volatile("cp.async.cg.shared.global [%0], [%1], 16;" :: "r"(dst), "l"(src));
}
#define CP_COMMIT() asm volatile("cp.async.commit_group;" ::: "memory")
#define CP_WAIT4()  asm volatile("cp.async.wait_group 4;" ::: "memory")

// ---------------------------------------------------------------------------
__global__ void embed_kernel(const float* __restrict__ state,
                             const float* __restrict__ ew,
                             const float* __restrict__ eb) {
    int idx = blockIdx.x * blockDim.x + threadIdx.x;
    int b = idx >> 9;
    int j = idx & 511;
    float s = eb[j];
    const float* sp = state + b * STATE;
#pragma unroll 8
    for (int k = 0; k < STATE; k++)
        s = fmaf(sp[k], ew[k * H + j], s);
    g_buf0[idx] = tanhf(s);
}

// ---------------------------------------------------------------------------
// fp16 m16n8k16 split-K GEMM, warp-decoupled:
//   - unscaled fp32 A fragments live in registers (refreshed per k-band,
//     CTA-cooperative staging with 2 syncthreads per 7-8 iterations)
//   - per-chunk scale applied at fragment pack time (rn16(a*sc), exact as before)
//   - B is warp-private: own cp.async 6-deep ring, own wait_group, no barriers
// CTA 128x128, 8 warps (2x4 of 64x32 warp tiles), 1 CTA/SM.
// ---------------------------------------------------------------------------
__global__ void __launch_bounds__(256, 1)
gemm_fp16(int layer, const float* __restrict__ cmd,
          const float* __restrict__ hwW, const float* __restrict__ hwb)
{
    extern __shared__ __align__(16) float sm[];
    float* sScale = sm;                       // [8][128]
    float* sA     = sm + 1024;                // [128][AW2] fp32, unscaled
    float* sBall  = sm + 1024 + 128 * AW2;    // [8 warps][STG][16][BSW]

    const int t    = threadIdx.x;
    const int lane = t & 31;
    const int w    = t >> 5;
    const int wm   = w & 1;
    const int wn   = w >> 1;
    const int q    = lane & 3;
    const int r4   = lane >> 2;

    const int n0 = blockIdx.x * 128;
    const int m0 = blockIdx.y * 128;
    const int sp = blockIdx.z;
    const int c0  = sp * 7 + (sp < 3 ? sp : 3);
    const int cnt = 7 + (sp < 3 ? 1 : 0);

    const float* __restrict__ inbuf = layer ? g_buf1 : g_buf0;

    // ---- A staging role ----
    const int am = t & 127;
    const int kh = t >> 7;
    const float* inrow = inbuf + (size_t)(m0 + am) * H + kh * 8;

    // ---- stage per-chunk scales [8][128] ----
#pragma unroll
    for (int i = 0; i < 4; i++) {
        int v = t * 4 + i;
        int c = v >> 7, row = v & 127;
        int d = c0 + c;
        sScale[c * 128 + row] =
            (c < cnt) ? ((d < DES) ? cmd[(m0 + row) * DES + d] : 1.0f) : 0.0f;
    }

    // ---- warp-private B ring ----
    float* myB = sBall + w * (STG * BSTW);
    const uint32_t myB_u32 = smem_u32(myB);
    const int brow = lane >> 1;                    // gmem row this lane copies
    const uint32_t bdst_row = myB_u32 + (uint32_t)(brow * BSW) * 4;
    const int bsrc_roff = brow * H + n0 + wn * 32;

    auto issueB = [&](int kbj, int cij, int slot) {
        int d = c0 + cij;
        const float* bb = ((d < DES) ? (hwW + (size_t)d * (H * H)) : hwb)
                          + ((size_t)kbj << 4) * H + bsrc_roff;
        uint32_t so = (uint32_t)slot * (BSTW * 4);
#pragma unroll
        for (int j = 0; j < 4; j++) {
            int ch = (4 * lane + j) & 7;           // 16B chunk within row
            cp16(bdst_row + so + (uint32_t)ch * 16, bb + ch * 4);
        }
        CP_COMMIT();
    };

    float acc[4][4][4];
#pragma unroll
    for (int i = 0; i < 4; i++)
#pragma unroll
        for (int j = 0; j < 4; j++)
#pragma unroll
            for (int k = 0; k < 4; k++) acc[i][j][k] = 0.0f;

    // prologue: 5 B stages in flight (kb=0, ci=0..4; cnt>=7)
#pragma unroll
    for (int i = 0; i < 5; i++) issueB(0, i, i);
    int kb_is = 0, ci_is = 5;

    float2 auf[4][4];   // unscaled fp32 A frags: [mi]{(r,2q),(r+8,2q),(r,2q+8),(r+8,2q+8)}
    const int arow = wm * 64 + r4;

    int it = 0;
    for (int kb = 0; kb < 32; kb++) {
        // ---- restage A band (CTA-cooperative, 2 syncs per 7-8 iters) ----
        __syncthreads();
        {
            float4 v0 = *(const float4*)(inrow + kb * 16);
            float4 v1 = *(const float4*)(inrow + kb * 16 + 4);
            float* ap = sA + am * AW2 + kh * 8;
            *(float4*)ap = v0;
            *(float4*)(ap + 4) = v1;
        }
        __syncthreads();
#pragma unroll
        for (int mi = 0; mi < 4; mi++) {
            int rb = arow + mi * 16;
            auf[mi][0] = *(const float2*)(sA + rb * AW2 + 2 * q);
            auf[mi][1] = *(const float2*)(sA + (rb + 8) * AW2 + 2 * q);
            auf[mi][2] = *(const float2*)(sA + rb * AW2 + 2 * q + 8);
            auf[mi][3] = *(const float2*)(sA + (rb + 8) * AW2 + 2 * q + 8);
        }

        for (int ci = 0; ci < cnt; ci++, it++) {
            CP_WAIT4();    // own group for slot it%STG complete (warp lockstep)

            // B fragments from warp-private slot
            const float* sb = myB + (it % STG) * BSTW;
            uint32_t bf[4][2];
#pragma unroll
            for (int ni = 0; ni < 4; ni++) {
                int col = ni * 8 + r4;
                float b0 = sb[(2 * q) * BSW + col];
                float b1 = sb[(2 * q + 1) * BSW + col];
                float b2 = sb[(2 * q + 8) * BSW + col];
                float b3 = sb[(2 * q + 9) * BSW + col];
                bf[ni][0] = pack_h2(b0, b1);
                bf[ni][1] = pack_h2(b2, b3);
            }

            // refill ring (slot (it+5)%STG was consumed at iter it-1)
            issueB(kb_is, ci_is, (it + 5) % STG);
            if (++ci_is == cnt) {
                ci_is = 0;
                if (++kb_is == 32) { kb_is = 31; ci_is = cnt - 1; }
            }

            // scaled A fragments (rn16(a*sc): same rounding as before)
            const float* scp = sScale + ci * 128;
#pragma unroll
            for (int mi = 0; mi < 4; mi++) {
                float s0 = scp[arow + mi * 16];
                float s1 = scp[arow + mi * 16 + 8];
                uint32_t a0 = pack_h2(auf[mi][0].x * s0, auf[mi][0].y * s0);
                uint32_t a1 = pack_h2(auf[mi][1].x * s1, auf[mi][1].y * s1);
                uint32_t a2 = pack_h2(auf[mi][2].x * s0, auf[mi][2].y * s0);
                uint32_t a3 = pack_h2(auf[mi][3].x * s1, auf[mi][3].y * s1);
#pragma unroll
                for (int ni = 0; ni < 4; ni++)
                    mma16816(acc[mi][ni], a0, a1, a2, a3, bf[ni][0], bf[ni][1]);
            }
        }
    }

    // ---- epilogue: write split-K partials ----
#pragma unroll
    for (int mi = 0; mi < 4; mi++) {
#pragma unroll
        for (int ni = 0; ni < 4; ni++) {
            int row = m0 + wm * 64 + mi * 16 + r4;
            int col = n0 + wn * 32 + ni * 8 + q * 2;
            *(float2*)&g_part[sp][row][col]     = make_float2(acc[mi][ni][0], acc[mi][ni][1]);
            *(float2*)&g_part[sp][row + 8][col] = make_float2(acc[mi][ni][2], acc[mi][ni][3]);
        }
    }
}

// ---------------------------------------------------------------------------
__global__ void reduce_bias_relu(const float* __restrict__ cmd,
                                 const float* __restrict__ hbW,
                                 const float* __restrict__ hbb,
                                 float* dst, int dst_is_buf1) {
    int idx = blockIdx.x * blockDim.x + threadIdx.x;
    int b = idx >> 9;
    int o = idx & 511;
    float s = hbb[o];
#pragma unroll
    for (int sp = 0; sp < SPLITS; sp++) s += g_part[sp][b][o];
    const float* cp = cmd + b * DES;
#pragma unroll 16
    for (int k = 0; k < DES; k++)
        s = fmaf(cp[k], hbW[k * H + o], s);
    float r = fmaxf(s, 0.0f);
    if (dst_is_buf1) g_buf1[idx] = r;
    else             dst[idx] = r;
}

// ---------------------------------------------------------------------------
extern "C" void kernel_launch(void* const* d_in, const int* in_sizes, int n_in,
                              void* d_out, int out_size) {
    const float* state = (const float*)d_in[0];
    const float* cmd   = (const float*)d_in[1];
    const float* ew    = (const float*)d_in[2];
    const float* eb    = (const float*)d_in[3];
    const float* hwW   = (const float*)d_in[4];
    const float* hwb   = (const float*)d_in[5];
    const float* hbW   = (const float*)d_in[6];
    const float* hbb   = (const float*)d_in[7];
    float* out = (float*)d_out;

    const size_t HWW_L = (size_t)DES * H * H;
    const size_t HWB_L = (size_t)H * H;
    const size_t HBW_L = (size_t)DES * H;
    const size_t HBB_L = (size_t)H;

    static int smem_set = 0;
    if (!smem_set) {
        cudaFuncSetAttribute(gemm_fp16, cudaFuncAttributeMaxDynamicSharedMemorySize, SMEM_BYTES);
        smem_set = 1;
    }

    embed_kernel<<<1024, 256>>>(state, ew, eb);

    dim3 grid(4, 4, SPLITS);

    gemm_fp16<<<grid, 256, SMEM_BYTES>>>(0, cmd, hwW, hwb);
    reduce_bias_relu<<<1024, 256>>>(cmd, hbW, hbb, out, 1);

    gemm_fp16<<<grid, 256, SMEM_BYTES>>>(1, cmd, hwW + HWW_L, hwb + HWB_L);
    reduce_bias_relu<<<1024, 256>>>(cmd, hbW + HBW_L, hbb + HBB_L, out, 0);
}

// round 8
// speedup vs baseline: 1.0847x; 1.0847x over previous
#include <cuda_runtime.h>
#include <cstdint>
#include <math.h>

#define BB    512
#define STATE 256
#define DES   128
#define H     512
#define SPLITS 18
#define STG   5     // B ring stages
#define SBW   132   // sB row stride (words) -> conflict-free B frag LDS, 16B-aligned rows
#define AW    12    // sA row stride (words, 48B) -> conflict-free STS.128 + ldmatrix

#define SA_WORDS (2 * 128 * AW)                       // 3072
#define SMEM_BYTES ((SA_WORDS + STG * 16 * SBW) * 4)  // 54528 -> 2 CTAs/SM

__device__ float g_buf0[BB * H];
__device__ float g_buf1[BB * H];
__device__ float g_part[SPLITS][BB][H];

__device__ __forceinline__ uint32_t pack_h2(float lo, float hi) {
    uint32_t r;
    asm("cvt.rn.f16x2.f32 %0, %1, %2;" : "=r"(r) : "f"(hi), "f"(lo));
    return r;
}
__device__ __forceinline__ void mma16816(float* c,
                                         uint32_t a0, uint32_t a1, uint32_t a2, uint32_t a3,
                                         uint32_t b0, uint32_t b1) {
    asm volatile("mma.sync.aligned.m16n8k16.row.col.f32.f16.f16.f32 "
                 "{%0,%1,%2,%3}, {%4,%5,%6,%7}, {%8,%9}, {%0,%1,%2,%3};"
                 : "+f"(c[0]), "+f"(c[1]), "+f"(c[2]), "+f"(c[3])
                 : "r"(a0), "r"(a1), "r"(a2), "r"(a3), "r"(b0), "r"(b1));
}
__device__ __forceinline__ uint32_t smem_u32(const void* p) {
    uint32_t a;
    asm("{ .reg .u64 t; cvta.to.shared.u64 t, %1; cvt.u32.u64 %0, t; }" : "=r"(a) : "l"(p));
    return a;
}
__device__ __forceinline__ void cp16(uint32_t dst, const float* src) {
    asm volatile("cp.async.cg.shared.global [%0], [%1], 16;" :: "r"(dst), "l"(src));
}
__device__ __forceinline__ void ldsm4(uint32_t& a0, uint32_t& a1, uint32_t& a2, uint32_t& a3,
                                      uint32_t addr) {
    asm volatile("ldmatrix.sync.aligned.m8n8.x4.shared.b16 {%0,%1,%2,%3}, [%4];"
                 : "=r"(a0), "=r"(a1), "=r"(a2), "=r"(a3) : "r"(addr));
}
__device__ __forceinline__ void sts128(uint32_t a, uint32_t x, uint32_t y, uint32_t z, uint32_t w) {
    asm volatile("st.shared.v4.b32 [%0], {%1,%2,%3,%4};" :: "r"(a), "r"(x), "r"(y), "r"(z), "r"(w) : "memory");
}
#define CP_COMMIT() asm volatile("cp.async.commit_group;" ::: "memory")
#define CP_WAIT3()  asm volatile("cp.async.wait_group 3;" ::: "memory")

// ---------------------------------------------------------------------------
__global__ void embed_kernel(const float* __restrict__ state,
                             const float* __restrict__ ew,
                             const float* __restrict__ eb) {
    int idx = blockIdx.x * blockDim.x + threadIdx.x;
    int b = idx >> 9;
    int j = idx & 511;
    float s = eb[j];
    const float* sp = state + b * STATE;
#pragma unroll 8
    for (int k = 0; k < STATE; k++)
        s = fmaf(sp[k], ew[k * H + j], s);
    g_buf0[idx] = tanhf(s);
}

// ---------------------------------------------------------------------------
// fp16 m16n8k16 split-K GEMM. 5-stage cp.async B ring, ldmatrix A,
// kb-outer loop. 2 CTAs/SM (54.5KB smem), single wave (288 CTAs / 296 slots).
//   virtual A[b, d*512+h] = cmd[b,d] * in[b,h]   (chunk d=128 -> hw_b, scale 1)
// ---------------------------------------------------------------------------
__global__ void __launch_bounds__(256, 2)
gemm_fp16(int layer, const float* __restrict__ cmd,
          const float* __restrict__ hwW, const float* __restrict__ hwb)
{
    extern __shared__ __align__(16) uint32_t smw[];
    float* sB = (float*)(smw + SA_WORDS);

    const int t    = threadIdx.x;
    const int lane = t & 31;
    const int w    = t >> 5;
    const int wm   = w & 1;
    const int wn   = w >> 1;
    const int q    = lane & 3;
    const int r4   = lane >> 2;

    const int n0 = blockIdx.x * 128;
    const int m0 = blockIdx.y * 128;
    const int sp = blockIdx.z;
    const int c0  = sp * 7 + (sp < 3 ? sp : 3);
    const int cnt = 7 + (sp < 3 ? 1 : 0);

    const float* __restrict__ inbuf = layer ? g_buf1 : g_buf0;

    // roles
    const int am = t & 127;
    const int kh = t >> 7;
    const float* inrow = inbuf + (size_t)(m0 + am) * H + kh * 8;

    const int brow = t >> 5;
    const int bcol4 = (t & 31) * 4;
    const uint32_t sA_u32 = smem_u32(smw);
    const uint32_t sB_u32 = smem_u32(sB);
    const uint32_t bdst1 = sB_u32 + (uint32_t)(brow * SBW + bcol4) * 4;
    const uint32_t bdst2 = bdst1 + 8 * SBW * 4;

    const uint32_t a_sts = sA_u32 + (uint32_t)(am * AW + kh * 4) * 4;
    const uint32_t a_ldm = sA_u32 + (uint32_t)((wm * 64 + (lane & 15)) * AW) * 4 + (lane >> 4) * 16;

    float sc[8];
#pragma unroll
    for (int i = 0; i < 8; i++) {
        int d = c0 + i;
        sc[i] = (i < cnt) ? ((d < DES) ? cmd[(m0 + am) * DES + d] : 1.0f) : 0.0f;
    }

    float acc[4][4][4];
#pragma unroll
    for (int i = 0; i < 4; i++)
#pragma unroll
        for (int j = 0; j < 4; j++)
#pragma unroll
            for (int k = 0; k < 4; k++) acc[i][j][k] = 0.0f;

    auto issueB = [&](int kbj, int cij, int slot) {
        int d = c0 + cij;
        const float* bb = ((d < DES) ? (hwW + (size_t)d * (H * H)) : hwb)
                          + ((size_t)kbj << 4) * H + n0;
        uint32_t so = (uint32_t)slot * (16 * SBW * 4);
        cp16(bdst1 + so, bb + brow * H + bcol4);
        cp16(bdst2 + so, bb + (brow + 8) * H + bcol4);
        CP_COMMIT();
    };

    // prologue: 4 stages in flight (iters 0..3 are kb=0, ci=0..3 since cnt>=7)
#pragma unroll
    for (int i = 0; i < 4; i++) issueB(0, i, i);
    int kb_is = 0, ci_is = 4;            // coords of iter 4

    float4 av0 = *(const float4*)(inrow);
    float4 av1 = *(const float4*)(inrow + 4);
    float4 nv0 = av0, nv1 = av1;

    int it = 0;
    for (int kb = 0; kb < 32; kb++) {
        for (int ci = 0; ci < cnt; ci++, it++) {
            const int buf = it & 1;
            const uint32_t bufoff = (uint32_t)buf * (128 * AW * 4);

            // stage A (scaled fp16, m-major row) — one STS.128
            {
                float s = sc[ci];
                sts128(a_sts + bufoff,
                       pack_h2(av0.x * s, av0.y * s), pack_h2(av0.z * s, av0.w * s),
                       pack_h2(av1.x * s, av1.y * s), pack_h2(av1.z * s, av1.w * s));
            }
            // prefetch next k-band of A (once per kb)
            if (ci == 0) {
                int kn = (kb < 31) ? kb + 1 : 31;
                nv0 = *(const float4*)(inrow + kn * 16);
                nv1 = *(const float4*)(inrow + kn * 16 + 4);
            }

            CP_WAIT3();
            __syncthreads();

            // keep ring full: issue iter it+4 (slot == (it-1)%STG, safe post-barrier)
            issueB(kb_is, ci_is, (it + 4) % STG);
            if (++ci_is == cnt) {
                ci_is = 0;
                if (++kb_is == 32) { kb_is = 31; ci_is = cnt - 1; }
            }

            // B fragments (fp32 -> f16x2)
            const float* sb = sB + (it % STG) * (16 * SBW);
            uint32_t bf[4][2];
#pragma unroll
            for (int ni = 0; ni < 4; ni++) {
                int col = wn * 32 + ni * 8 + r4;
                float b0 = sb[(2 * q) * SBW + col];
                float b1 = sb[(2 * q + 1) * SBW + col];
                float b2 = sb[(2 * q + 8) * SBW + col];
                float b3 = sb[(2 * q + 9) * SBW + col];
                bf[ni][0] = pack_h2(b0, b1);
                bf[ni][1] = pack_h2(b2, b3);
            }
            // A fragments via ldmatrix + MMAs
#pragma unroll
            for (int mi = 0; mi < 4; mi++) {
                uint32_t a0, a1, a2, a3;
                ldsm4(a0, a1, a2, a3, a_ldm + bufoff + (uint32_t)(mi * 16 * AW) * 4);
#pragma unroll
                for (int ni = 0; ni < 4; ni++)
                    mma16816(acc[mi][ni], a0, a1, a2, a3, bf[ni][0], bf[ni][1]);
            }
        }
        av0 = nv0; av1 = nv1;
    }

    // epilogue: write split-K partials
#pragma unroll
    for (int mi = 0; mi < 4; mi++) {
#pragma unroll
        for (int ni = 0; ni < 4; ni++) {
            int row = m0 + wm * 64 + mi * 16 + r4;
            int col = n0 + wn * 32 + ni * 8 + q * 2;
            *(float2*)&g_part[sp][row][col]     = make_float2(acc[mi][ni][0], acc[mi][ni][1]);
            *(float2*)&g_part[sp][row + 8][col] = make_float2(acc[mi][ni][2], acc[mi][ni][3]);
        }
    }
}

// ---------------------------------------------------------------------------
__global__ void reduce_bias_relu(const float* __restrict__ cmd,
                                 const float* __restrict__ hbW,
                                 const float* __restrict__ hbb,
                                 float* dst, int dst_is_buf1) {
    int idx = blockIdx.x * blockDim.x + threadIdx.x;
    int b = idx >> 9;
    int o = idx & 511;
    float s = hbb[o];
#pragma unroll
    for (int sp = 0; sp < SPLITS; sp++) s += g_part[sp][b][o];
    const float* cp = cmd + b * DES;
#pragma unroll 16
    for (int k = 0; k < DES; k++)
        s = fmaf(cp[k], hbW[k * H + o], s);
    float r = fmaxf(s, 0.0f);
    if (dst_is_buf1) g_buf1[idx] = r;
    else             dst[idx] = r;
}

// ---------------------------------------------------------------------------
extern "C" void kernel_launch(void* const* d_in, const int* in_sizes, int n_in,
                              void* d_out, int out_size) {
    const float* state = (const float*)d_in[0];
    const float* cmd   = (const float*)d_in[1];
    const float* ew    = (const float*)d_in[2];
    const float* eb    = (const float*)d_in[3];
    const float* hwW   = (const float*)d_in[4];
    const float* hwb   = (const float*)d_in[5];
    const float* hbW   = (const float*)d_in[6];
    const float* hbb   = (const float*)d_in[7];
    float* out = (float*)d_out;

    const size_t HWW_L = (size_t)DES * H * H;
    const size_t HWB_L = (size_t)H * H;
    const size_t HBW_L = (size_t)DES * H;
    const size_t HBB_L = (size_t)H;

    static int smem_set = 0;
    if (!smem_set) {
        cudaFuncSetAttribute(gemm_fp16, cudaFuncAttributeMaxDynamicSharedMemorySize, SMEM_BYTES);
        smem_set = 1;
    }

    embed_kernel<<<1024, 256>>>(state, ew, eb);

    dim3 grid(4, 4, SPLITS);

    gemm_fp16<<<grid, 256, SMEM_BYTES>>>(0, cmd, hwW, hwb);
    reduce_bias_relu<<<1024, 256>>>(cmd, hbW, hbb, out, 1);

    gemm_fp16<<<grid, 256, SMEM_BYTES>>>(1, cmd, hwW + HWW_L, hwb + HWB_L);
    reduce_bias_relu<<<1024, 256>>>(cmd, hbW + HBW_L, hbb + HBB_L, out, 0);
}

// round 9
// speedup vs baseline: 1.6160x; 1.4898x over previous
#include <cuda_runtime.h>
#include <cstdint>
#include <math.h>

#define BB    512
#define STATE 256
#define DES   128
#define H     512
#define SPLITS 18
#define STG   8     // B ring stages (deep pipeline)
#define SBW   140   // sB row stride (words) -> conflict-free B frag LDS
#define AW    12    // sA row stride (words, 48B) -> conflict-free STS.128 + ldmatrix

#define SA_WORDS (2 * 128 * AW)                       // 3072
#define SMEM_BYTES ((SA_WORDS + STG * 16 * SBW) * 4)  // 83968 (2 CTAs/SM: 164KB < 228KB)

__device__ float g_buf0[BB * H];
__device__ float g_buf1[BB * H];
__device__ float g_part[SPLITS][BB][H];

__device__ __forceinline__ uint32_t pack_h2(float lo, float hi) {
    uint32_t r;
    asm("cvt.rn.f16x2.f32 %0, %1, %2;" : "=r"(r) : "f"(hi), "f"(lo));
    return r;
}
__device__ __forceinline__ void mma16816(float* c,
                                         uint32_t a0, uint32_t a1, uint32_t a2, uint32_t a3,
                                         uint32_t b0, uint32_t b1) {
    asm volatile("mma.sync.aligned.m16n8k16.row.col.f32.f16.f16.f32 "
                 "{%0,%1,%2,%3}, {%4,%5,%6,%7}, {%8,%9}, {%0,%1,%2,%3};"
                 : "+f"(c[0]), "+f"(c[1]), "+f"(c[2]), "+f"(c[3])
                 : "r"(a0), "r"(a1), "r"(a2), "r"(a3), "r"(b0), "r"(b1));
}
__device__ __forceinline__ uint32_t smem_u32(const void* p) {
    uint32_t a;
    asm("{ .reg .u64 t; cvta.to.shared.u64 t, %1; cvt.u32.u64 %0, t; }" : "=r"(a) : "l"(p));
    return a;
}
__device__ __forceinline__ void cp16(uint32_t dst, const float* src) {
    asm volatile("cp.async.cg.shared.global [%0], [%1], 16;" :: "r"(dst), "l"(src));
}
__device__ __forceinline__ void ldsm4(uint32_t& a0, uint32_t& a1, uint32_t& a2, uint32_t& a3,
                                      uint32_t addr) {
    asm volatile("ldmatrix.sync.aligned.m8n8.x4.shared.b16 {%0,%1,%2,%3}, [%4];"
                 : "=r"(a0), "=r"(a1), "=r"(a2), "=r"(a3) : "r"(addr));
}
__device__ __forceinline__ void sts128(uint32_t a, uint32_t x, uint32_t y, uint32_t z, uint32_t w) {
    asm volatile("st.shared.v4.b32 [%0], {%1,%2,%3,%4};" :: "r"(a), "r"(x), "r"(y), "r"(z), "r"(w) : "memory");
}
#define CP_COMMIT() asm volatile("cp.async.commit_group;" ::: "memory")
#define CP_WAIT6()  asm volatile("cp.async.wait_group 6;" ::: "memory")

// ---------------------------------------------------------------------------
__global__ void embed_kernel(const float* __restrict__ state,
                             const float* __restrict__ ew,
                             const float* __restrict__ eb) {
    int idx = blockIdx.x * blockDim.x + threadIdx.x;
    int b = idx >> 9;
    int j = idx & 511;
    float s = eb[j];
    const float* sp = state + b * STATE;
#pragma unroll 8
    for (int k = 0; k < STATE; k++)
        s = fmaf(sp[k], ew[k * H + j], s);
    g_buf0[idx] = tanhf(s);
}

// ---------------------------------------------------------------------------
// fp16 m16n8k16 split-K GEMM. 8-stage cp.async B ring (prefetch depth 7),
// ldmatrix A, kb-outer loop, 2 CTAs/SM.
//   virtual A[b, d*512+h] = cmd[b,d] * in[b,h]   (chunk d=128 -> hw_b, scale 1)
// ---------------------------------------------------------------------------
__global__ void __launch_bounds__(256, 2)
gemm_fp16(int layer, const float* __restrict__ cmd,
          const float* __restrict__ hwW, const float* __restrict__ hwb)
{
    extern __shared__ __align__(16) uint32_t smw[];
    float* sB = (float*)(smw + SA_WORDS);

    const int t    = threadIdx.x;
    const int lane = t & 31;
    const int w    = t >> 5;
    const int wm   = w & 1;
    const int wn   = w >> 1;
    const int q    = lane & 3;
    const int r4   = lane >> 2;

    const int n0 = blockIdx.x * 128;
    const int m0 = blockIdx.y * 128;
    const int sp = blockIdx.z;
    const int c0  = sp * 7 + (sp < 3 ? sp : 3);
    const int cnt = 7 + (sp < 3 ? 1 : 0);

    const float* __restrict__ inbuf = layer ? g_buf1 : g_buf0;

    // roles
    const int am = t & 127;
    const int kh = t >> 7;
    const float* inrow = inbuf + (size_t)(m0 + am) * H + kh * 8;

    const int brow = t >> 5;
    const int bcol4 = (t & 31) * 4;
    const uint32_t sA_u32 = smem_u32(smw);
    const uint32_t sB_u32 = smem_u32(sB);
    const uint32_t bdst1 = sB_u32 + (uint32_t)(brow * SBW + bcol4) * 4;
    const uint32_t bdst2 = bdst1 + 8 * SBW * 4;

    const uint32_t a_sts = sA_u32 + (uint32_t)(am * AW + kh * 4) * 4;
    const uint32_t a_ldm = sA_u32 + (uint32_t)((wm * 64 + (lane & 15)) * AW) * 4 + (lane >> 4) * 16;

    float sc[8];
#pragma unroll
    for (int i = 0; i < 8; i++) {
        int d = c0 + i;
        sc[i] = (i < cnt) ? ((d < DES) ? cmd[(m0 + am) * DES + d] : 1.0f) : 0.0f;
    }

    float acc[4][4][4];
#pragma unroll
    for (int i = 0; i < 4; i++)
#pragma unroll
        for (int j = 0; j < 4; j++)
#pragma unroll
            for (int k = 0; k < 4; k++) acc[i][j][k] = 0.0f;

    auto issueB = [&](int kbj, int cij, int slot) {
        int d = c0 + cij;
        const float* bb = ((d < DES) ? (hwW + (size_t)d * (H * H)) : hwb)
                          + ((size_t)kbj << 4) * H + n0;
        uint32_t so = (uint32_t)slot * (16 * SBW * 4);
        cp16(bdst1 + so, bb + brow * H + bcol4);
        cp16(bdst2 + so, bb + (brow + 8) * H + bcol4);
        CP_COMMIT();
    };

    // prologue: 7 stages in flight (iters 0..6 are kb=0, ci=0..6 since cnt>=7)
#pragma unroll
    for (int i = 0; i < 7; i++) issueB(0, i, i);
    int kb_is = 0, ci_is = 7;            // coords of iter 7
    if (ci_is >= cnt) { ci_is -= cnt; kb_is = 1; }

    float4 av0 = *(const float4*)(inrow);
    float4 av1 = *(const float4*)(inrow + 4);
    float4 nv0 = av0, nv1 = av1;

    int it = 0;
    for (int kb = 0; kb < 32; kb++) {
        for (int ci = 0; ci < cnt; ci++, it++) {
            const int buf = it & 1;
            const uint32_t bufoff = (uint32_t)buf * (128 * AW * 4);

            // stage A (scaled fp16, m-major row) — one STS.128
            {
                float s = sc[ci];
                sts128(a_sts + bufoff,
                       pack_h2(av0.x * s, av0.y * s), pack_h2(av0.z * s, av0.w * s),
                       pack_h2(av1.x * s, av1.y * s), pack_h2(av1.z * s, av1.w * s));
            }
            // prefetch next k-band of A (once per kb)
            if (ci == 0) {
                int kn = (kb < 31) ? kb + 1 : 31;
                nv0 = *(const float4*)(inrow + kn * 16);
                nv1 = *(const float4*)(inrow + kn * 16 + 4);
            }

            CP_WAIT6();
            __syncthreads();

            // keep ring full: issue iter it+7 (slot == (it-1)%STG, safe post-barrier)
            issueB(kb_is, ci_is, (it + 7) % STG);
            if (++ci_is == cnt) {
                ci_is = 0;
                if (++kb_is == 32) { kb_is = 31; ci_is = cnt - 1; }
            }

            // B fragments (fp32 -> f16x2)
            const float* sb = sB + (it % STG) * (16 * SBW);
            uint32_t bf[4][2];
#pragma unroll
            for (int ni = 0; ni < 4; ni++) {
                int col = wn * 32 + ni * 8 + r4;
                float b0 = sb[(2 * q) * SBW + col];
                float b1 = sb[(2 * q + 1) * SBW + col];
                float b2 = sb[(2 * q + 8) * SBW + col];
                float b3 = sb[(2 * q + 9) * SBW + col];
                bf[ni][0] = pack_h2(b0, b1);
                bf[ni][1] = pack_h2(b2, b3);
            }
            // A fragments via ldmatrix + MMAs
#pragma unroll
            for (int mi = 0; mi < 4; mi++) {
                uint32_t a0, a1, a2, a3;
                ldsm4(a0, a1, a2, a3, a_ldm + bufoff + (uint32_t)(mi * 16 * AW) * 4);
#pragma unroll
                for (int ni = 0; ni < 4; ni++)
                    mma16816(acc[mi][ni], a0, a1, a2, a3, bf[ni][0], bf[ni][1]);
            }
        }
        av0 = nv0; av1 = nv1;
    }

    // epilogue: write split-K partials
#pragma unroll
    for (int mi = 0; mi < 4; mi++) {
#pragma unroll
        for (int ni = 0; ni < 4; ni++) {
            int row = m0 + wm * 64 + mi * 16 + r4;
            int col = n0 + wn * 32 + ni * 8 + q * 2;
            *(float2*)&g_part[sp][row][col]     = make_float2(acc[mi][ni][0], acc[mi][ni][1]);
            *(float2*)&g_part[sp][row + 8][col] = make_float2(acc[mi][ni][2], acc[mi][ni][3]);
        }
    }
}

// ---------------------------------------------------------------------------
__global__ void reduce_bias_relu(const float* __restrict__ cmd,
                                 const float* __restrict__ hbW,
                                 const float* __restrict__ hbb,
                                 float* dst, int dst_is_buf1) {
    int idx = blockIdx.x * blockDim.x + threadIdx.x;
    int b = idx >> 9;
    int o = idx & 511;
    float s = hbb[o];
#pragma unroll
    for (int sp = 0; sp < SPLITS; sp++) s += g_part[sp][b][o];
    const float* cp = cmd + b * DES;
#pragma unroll 16
    for (int k = 0; k < DES; k++)
        s = fmaf(cp[k], hbW[k * H + o], s);
    float r = fmaxf(s, 0.0f);
    if (dst_is_buf1) g_buf1[idx] = r;
    else             dst[idx] = r;
}

// ---------------------------------------------------------------------------
extern "C" void kernel_launch(void* const* d_in, const int* in_sizes, int n_in,
                              void* d_out, int out_size) {
    const float* state = (const float*)d_in[0];
    const float* cmd   = (const float*)d_in[1];
    const float* ew    = (const float*)d_in[2];
    const float* eb    = (const float*)d_in[3];
    const float* hwW   = (const float*)d_in[4];
    const float* hwb   = (const float*)d_in[5];
    const float* hbW   = (const float*)d_in[6];
    const float* hbb   = (const float*)d_in[7];
    float* out = (float*)d_out;

    const size_t HWW_L = (size_t)DES * H * H;
    const size_t HWB_L = (size_t)H * H;
    const size_t HBW_L = (size_t)DES * H;
    const size_t HBB_L = (size_t)H;

    static int smem_set = 0;
    if (!smem_set) {
        cudaFuncSetAttribute(gemm_fp16, cudaFuncAttributeMaxDynamicSharedMemorySize, SMEM_BYTES);
        smem_set = 1;
    }

    embed_kernel<<<1024, 256>>>(state, ew, eb);

    dim3 grid(4, 4, SPLITS);

    gemm_fp16<<<grid, 256, SMEM_BYTES>>>(0, cmd, hwW, hwb);
    reduce_bias_relu<<<1024, 256>>>(cmd, hbW, hbb, out, 1);

    gemm_fp16<<<grid, 256, SMEM_BYTES>>>(1, cmd, hwW + HWW_L, hwb + HWB_L);
    reduce_bias_relu<<<1024, 256>>>(cmd, hbW + HBW_L, hbb + HBB_L, out, 0);
}